// round 9
// baseline (speedup 1.0000x reference)
#include <cuda_runtime.h>

#define N_NODES 100000
#define N_EDGES 1600000
#define D 128

// Scratch for h = x @ W  (51.2 MB, __device__ global per allocation rules)
__device__ float g_h[(size_t)N_NODES * D];

// ---------------------------------------------------------------------------
// GEMM: g_h = x @ W   (M=100000, N=128, K=128), fp32 with packed fma.rn.f32x2
// Block tile 128x128, 256 threads, 8x8 micro-tile per thread.
// ---------------------------------------------------------------------------
#define BM 128
#define BK 16

__global__ __launch_bounds__(256) void gemm_kernel(const float* __restrict__ x,
                                                   const float* __restrict__ W) {
    __shared__ float As[BK][BM];   // k-major: As[k][m]
    __shared__ float Bs[BK][D];    // Bs[k][n]

    const int tid = threadIdx.x;
    const int tx = tid & 15;       // 16 threads across N
    const int ty = tid >> 4;       // 16 threads across M
    const int m0 = blockIdx.x * BM;

    unsigned long long acc[8][4];
    #pragma unroll
    for (int i = 0; i < 8; i++)
        #pragma unroll
        for (int j = 0; j < 4; j++) acc[i][j] = 0ULL;

    for (int k0 = 0; k0 < D; k0 += BK) {
        // Load A tile (transpose to k-major). 128x16 floats = 512 float4.
        #pragma unroll
        for (int it = 0; it < 2; it++) {
            int idx = it * 256 + tid;        // 0..511
            int m = idx >> 2;                // 0..127
            int c = idx & 3;                 // which float4 along k
            int row = m0 + m;
            float4 v = make_float4(0.f, 0.f, 0.f, 0.f);
            if (row < N_NODES)
                v = *(const float4*)&x[(size_t)row * D + k0 + c * 4];
            As[c * 4 + 0][m] = v.x;
            As[c * 4 + 1][m] = v.y;
            As[c * 4 + 2][m] = v.z;
            As[c * 4 + 3][m] = v.w;
        }
        // Load B tile: 16x128 floats = 512 float4, coalesced.
        #pragma unroll
        for (int it = 0; it < 2; it++) {
            int idx = it * 256 + tid;        // 0..511
            int kk = idx >> 5;               // 0..15
            int nq = idx & 31;               // float4 index along n
            *(float4*)&Bs[kk][nq * 4] =
                *(const float4*)&W[(size_t)(k0 + kk) * D + nq * 4];
        }
        __syncthreads();

        #pragma unroll
        for (int kk = 0; kk < BK; kk++) {
            float4 a0 = *(const float4*)&As[kk][ty * 8];
            float4 a1 = *(const float4*)&As[kk][ty * 8 + 4];
            unsigned long long b[4];
            #pragma unroll
            for (int j = 0; j < 4; j++)
                b[j] = *(const unsigned long long*)&Bs[kk][tx * 8 + j * 2];
            float a[8] = {a0.x, a0.y, a0.z, a0.w, a1.x, a1.y, a1.z, a1.w};
            #pragma unroll
            for (int i = 0; i < 8; i++) {
                unsigned long long aa;
                asm("mov.b64 %0, {%1, %1};" : "=l"(aa) : "r"(__float_as_uint(a[i])));
                #pragma unroll
                for (int j = 0; j < 4; j++)
                    asm("fma.rn.f32x2 %0, %1, %2, %0;"
                        : "+l"(acc[i][j]) : "l"(aa), "l"(b[j]));
            }
        }
        __syncthreads();
    }

    // Store 8x8 per thread (as 4 x 8-byte packed stores per row).
    #pragma unroll
    for (int i = 0; i < 8; i++) {
        int row = m0 + ty * 8 + i;
        if (row < N_NODES) {
            #pragma unroll
            for (int j = 0; j < 4; j++)
                *(unsigned long long*)&g_h[(size_t)row * D + tx * 8 + j * 2] = acc[i][j];
        }
    }
}

// ---------------------------------------------------------------------------
// Init: out[n][d] = bias[d]  (out is poisoned 0xAA; atomics accumulate on top)
// ---------------------------------------------------------------------------
__global__ __launch_bounds__(256) void init_out_kernel(float* __restrict__ out,
                                                       const float* __restrict__ bias) {
    size_t idx = (size_t)blockIdx.x * blockDim.x + threadIdx.x;  // float4 index
    const size_t total = (size_t)N_NODES * D / 4;
    if (idx < total) {
        float4 bv = ((const float4*)bias)[idx & 31];  // 32 float4 per row
        ((float4*)out)[idx] = bv;
    }
}

// ---------------------------------------------------------------------------
// Scatter: one warp per edge. Each lane handles 16 B of the 512 B row.
//   msg = relu(h[src] + edge_attr[e]);  out[dst] += msg  via red.global.v4.f32
//
// edge_index dtype is sniffed on-device: the reference says int64, but JAX
// downcasts to int32 without x64 mode. Interpreting int32 data as int64
// yields values >= 2^32 with overwhelming probability (4 independent checks:
// P(misdetect) ~ 1e-20), so the check is robust and deterministic.
// ---------------------------------------------------------------------------
__global__ __launch_bounds__(256) void scatter_kernel(const void* __restrict__ ei_raw,
                                                      const float* __restrict__ ea,
                                                      float* __restrict__ out) {
    const long long* ei64 = (const long long*)ei_raw;
    const int*       ei32 = (const int*)ei_raw;

    const int lane = threadIdx.x & 31;
    const int warp = (int)((blockIdx.x * blockDim.x + threadIdx.x) >> 5);
    const int nwarps = (int)((gridDim.x * blockDim.x) >> 5);

    // Dtype sniff (lane 0 of every warp; cheap, L2/L1-hit after first warp).
    int is64 = 0;
    if (lane == 0) {
        is64 = 1;
        #pragma unroll
        for (int i = 0; i < 4; i++) {
            long long v = __ldg(&ei64[i]);
            if (v < 0 || v >= N_NODES) is64 = 0;
        }
    }
    is64 = __shfl_sync(0xffffffffu, is64, 0);

    for (int e = warp; e < N_EDGES; e += nwarps) {
        long long s = 0, d = 0;
        if (lane == 0) {
            if (is64) {
                s = __ldg(&ei64[e]);
                d = __ldg(&ei64[N_EDGES + e]);
            } else {
                s = __ldg(&ei32[e]);
                d = __ldg(&ei32[N_EDGES + e]);
            }
        }
        s = __shfl_sync(0xffffffffu, s, 0);
        d = __shfl_sync(0xffffffffu, d, 0);

        const float4* hp = (const float4*)&g_h[(size_t)s * D] + lane;  // L2-resident
        const float4* ep = (const float4*)&ea[(size_t)e * D] + lane;   // streamed once
        float4 hv = __ldg(hp);
        float4 ev = __ldcs(ep);

        float4 r;
        r.x = fmaxf(hv.x + ev.x, 0.f);
        r.y = fmaxf(hv.y + ev.y, 0.f);
        r.z = fmaxf(hv.z + ev.z, 0.f);
        r.w = fmaxf(hv.w + ev.w, 0.f);

        float* op = out + (size_t)d * D + lane * 4;
        asm volatile("red.global.add.v4.f32 [%0], {%1, %2, %3, %4};"
                     :: "l"(op), "f"(r.x), "f"(r.y), "f"(r.z), "f"(r.w)
                     : "memory");
    }
}

// ---------------------------------------------------------------------------
extern "C" void kernel_launch(void* const* d_in, const int* in_sizes, int n_in,
                              void* d_out, int out_size) {
    (void)in_sizes; (void)n_in; (void)out_size;
    const float* x    = (const float*)d_in[0];
    const void*  ei   = d_in[1];
    const float* ea   = (const float*)d_in[2];
    const float* W    = (const float*)d_in[3];
    const float* bias = (const float*)d_in[4];
    float*       out  = (float*)d_out;

    // h = x @ W
    gemm_kernel<<<(N_NODES + BM - 1) / BM, 256>>>(x, W);
    // out = bias (broadcast)
    init_out_kernel<<<(N_NODES * D / 4 + 255) / 256, 256>>>(out, bias);
    // out[dst] += relu(h[src] + edge_attr)
    scatter_kernel<<<N_EDGES / 8, 256>>>(ei, ea, out);
}